// round 14
// baseline (speedup 1.0000x reference)
#include <cuda_runtime.h>
#include <math.h>

// Shapes (fixed by the problem)
//  x       [16][16][4096]
//  conv_w  [256][16][9]
//  conv_b  [256]
//  caps_w  [8][16][256]
//  caps_b  [8][16]
//  W       [8][16][16]
//  out     [8][16][8][4096]  (n0, k, n, s)
//
// Algebra:
//  s0[n0,k,n,s] = Weff[n,k] (*) xc[n0,k] + beff           (xc = Σ_b C[n0,k,b]·x[b], ΣC=1)
//  U[k,n,s]     = Weff[n,k] (*) xU + 16·beff              (xU = Σ_b x[b])
//  s1 = s0·(1 + f0·s0·U); s2 = s0 + f1·s1²·U; out = f2·s2; f(SS)=√SS/(1+SS), SS=Σ_s s²

__device__ float g_Weff[128 * 144];      // [n*16+k][ic*9+dk]
__device__ float g_beff[128];            // [n*16+k]
__device__ float g_xc[128 * 16 * 4096];  // [n0*16+k][ic][s]   (32 MB)
__device__ float g_xU[16 * 4096];        // [ic][s]
__device__ float g_U[128 * 4096];        // [k*8+n][s]          (2 MB)
__device__ float g_s0[1024 * 4096];      // [n0*128+k*8+n][s]   (16 MB)

__device__ __forceinline__ void ffma2(unsigned long long& d,
                                      unsigned long long a,
                                      unsigned long long b) {
    asm("fma.rn.f32x2 %0, %1, %2, %0;" : "+l"(d) : "l"(a), "l"(b));
}

// ---------------------------------------------------------------------------
// K0 (k_pre): flat grid of 641 blocks:
//   bx < 512  : xc/xU tile. ic = bx>>5, stile = (bx>>1)&15 (256 s), half = bx&1
//               (64 nk per block, 2 s per thread)
//   512..639  : Weff row nk = bx-512
//   640       : beff
// ---------------------------------------------------------------------------
__global__ __launch_bounds__(160) void k_pre(const float* __restrict__ x,
                                             const float* __restrict__ Wr,
                                             const float* __restrict__ caps_w,
                                             const float* __restrict__ conv_w,
                                             const float* __restrict__ conv_b,
                                             const float* __restrict__ caps_b) {
    const int bx = blockIdx.x;
    const int tid = threadIdx.x;

    if (bx >= 512) {
        if (bx == 640) {
            if (tid < 128) {
                float acc = caps_b[tid];
                for (int oc = 0; oc < 256; oc++)
                    acc += caps_w[tid * 256 + oc] * conv_b[oc];
                g_beff[tid] = acc;
            }
            return;
        }
        int nk = bx - 512;
        __shared__ float cw[256];
        for (int i = tid; i < 256; i += 160)
            cw[i] = caps_w[nk * 256 + i];
        __syncthreads();
        if (tid < 144) {
            int ic = tid / 9, dk = tid - ic * 9;
            float acc = 0.f;
            for (int oc = 0; oc < 256; oc++)
                acc += cw[oc] * conv_w[(oc * 16 + ic) * 9 + dk];
            g_Weff[nk * 144 + tid] = acc;
        }
        return;
    }

    // --- xc block ---
    const int ic    = bx >> 5;
    const int sbase = ((bx >> 1) & 15) * 256;
    const int nk0   = (bx & 1) * 64;

    __shared__ __align__(16) float xs[16][256];
    __shared__ float Cs[64][16];

    // softmax rows for this block's 64 nk (thread t<64 -> global nk0+t)
    if (tid < 64) {
        int nkg = nk0 + tid;
        int n0 = nkg >> 4, k = nkg & 15;
        float m = -1e30f;
        float e[16];
        #pragma unroll
        for (int b = 0; b < 16; b++)
            m = fmaxf(m, Wr[(n0 * 16 + b) * 16 + k]);
        float sum = 0.f;
        #pragma unroll
        for (int b = 0; b < 16; b++) {
            float v = expf(Wr[(n0 * 16 + b) * 16 + k] - m);
            e[b] = v;
            sum += v;
        }
        float inv = 1.f / sum;
        #pragma unroll
        for (int b = 0; b < 16; b++)
            Cs[tid][b] = e[b] * inv;
    }
    for (int idx = tid; idx < 16 * 64; idx += 160) {
        int b = idx >> 6, q = idx & 63;
        float4 v = *reinterpret_cast<const float4*>(&x[(b * 16 + ic) * 4096 + sbase + q * 4]);
        *reinterpret_cast<float4*>(&xs[b][q * 4]) = v;
    }
    __syncthreads();

    if (tid >= 128) return;

    float xb[16][2];
    #pragma unroll
    for (int b = 0; b < 16; b++) {
        float2 v = *reinterpret_cast<const float2*>(&xs[b][tid * 2]);
        xb[b][0] = v.x; xb[b][1] = v.y;
    }

    if (nk0 == 0) {   // xU once (half 0 only)
        float u0 = 0.f, u1 = 0.f;
        #pragma unroll
        for (int b = 0; b < 16; b++) { u0 += xb[b][0]; u1 += xb[b][1]; }
        *reinterpret_cast<float2*>(&g_xU[ic * 4096 + sbase + tid * 2]) = make_float2(u0, u1);
    }

    for (int j = 0; j < 64; j++) {
        float a0 = 0.f, a1 = 0.f;
        #pragma unroll
        for (int b = 0; b < 16; b++) {
            float c = Cs[j][b];
            a0 = fmaf(c, xb[b][0], a0);
            a1 = fmaf(c, xb[b][1], a1);
        }
        *reinterpret_cast<float2*>(&g_xc[((nk0 + j) * 16 + ic) * 4096 + sbase + tid * 2]) =
            make_float2(a0, a1);
    }
}

// ---------------------------------------------------------------------------
// K1: fused conv (s0 + U) with packed FFMA2 + skewed x tile.  (unchanged)
// grid (stile=16 of 256, y=144): y<128 -> s0 block (n0k=y); y>=128 -> U (k=y-128)
// block 128 thr: n = tid&7 (capsule), g = tid>>3 (s-subtile of 16)
// ---------------------------------------------------------------------------
#define XT_ROW 306   // 17 blocks * 18 floats

__global__ __launch_bounds__(128) void k_conv() {
    const int sc = blockIdx.x * 256;
    const int y  = blockIdx.y;
    const bool isU = (y >= 128);
    const int k = isU ? (y - 128) : (y & 15);
    const int tid = threadIdx.x;
    const int n = tid & 7;
    const int g = tid >> 3;

    __shared__ __align__(16) float xt[16 * XT_ROW];
    __shared__ __align__(8) float2 ws2[8][145];
    __shared__ float bs[8];

    const float* src = isU ? g_xU : &g_xc[(y * 16) * 4096];
    for (int j = tid; j < 16 * 264; j += 128) {
        int ic = j / 264, jj = j - ic * 264;
        int s = sc - 4 + jj;
        int phys = ((jj >> 4) * 18) + (jj & 15);
        xt[ic * XT_ROW + phys] = (s >= 0 && s < 4096) ? src[ic * 4096 + s] : 0.f;
    }
    for (int i = tid; i < 8 * 144; i += 128) {
        int n2 = i / 144, j = i - n2 * 144;
        float w = g_Weff[(n2 * 16 + k) * 144 + j];
        ws2[n2][j] = make_float2(w, w);
    }
    if (tid < 8) bs[tid] = g_beff[tid * 16 + k] * (isU ? 16.f : 1.f);
    __syncthreads();

    const float bv = bs[n];
    unsigned long long A[8], B[9];
    {
        float2 bp = make_float2(bv, bv);
        unsigned long long bu;
        __builtin_memcpy(&bu, &bp, 8);
        #pragma unroll
        for (int j = 0; j < 8; j++) A[j] = bu;
        #pragma unroll
        for (int j = 0; j < 9; j++) B[j] = 0ull;
    }

    const unsigned long long* wrow = reinterpret_cast<const unsigned long long*>(&ws2[n][0]);
    const int p0off = g * 18;
    const int p1off = (g + 1) * 18;

    #pragma unroll
    for (int ic = 0; ic < 16; ic++) {
        const float* row = &xt[ic * XT_ROW];
        unsigned long long E[12];
        #pragma unroll
        for (int j = 0; j < 8; j++)
            E[j] = *reinterpret_cast<const unsigned long long*>(row + p0off + 2 * j);
        #pragma unroll
        for (int m = 0; m < 4; m++)
            E[8 + m] = *reinterpret_cast<const unsigned long long*>(row + p1off + 2 * m);

        const unsigned long long* wp = wrow + ic * 9;
        #pragma unroll
        for (int e = 0; e < 5; e++) {
            unsigned long long w = wp[2 * e];
            #pragma unroll
            for (int j = 0; j < 8; j++) ffma2(A[j], w, E[j + e]);
        }
        #pragma unroll
        for (int o = 0; o < 4; o++) {
            unsigned long long w = wp[2 * o + 1];
            #pragma unroll
            for (int j = 0; j < 9; j++) ffma2(B[j], w, E[j + o]);
        }
    }

    float2 a[8], b[9];
    #pragma unroll
    for (int j = 0; j < 8; j++) __builtin_memcpy(&a[j], &A[j], 8);
    #pragma unroll
    for (int j = 0; j < 9; j++) __builtin_memcpy(&b[j], &B[j], 8);

    float res[16];
    #pragma unroll
    for (int j = 0; j < 8; j++) {
        res[2 * j]     = a[j].x + b[j].y;
        res[2 * j + 1] = a[j].y + b[j + 1].x;
    }

    const int sb = g * 16;
    float* orow = isU ? &g_U[(k * 8 + n) * 4096 + sc]
                      : &g_s0[(((y >> 4) * 128) + k * 8 + n) * 4096 + sc];
    #pragma unroll
    for (int q = 0; q < 4; q++)
        *reinterpret_cast<float4*>(&orow[sb + q * 4]) =
            make_float4(res[q * 4], res[q * 4 + 1], res[q * 4 + 2], res[q * 4 + 3]);
}

// ---------------------------------------------------------------------------
// K2: squash — register-resident, coalesced.  (unchanged)
// ---------------------------------------------------------------------------
__device__ __forceinline__ float block_reduce(float p, float* red, int tid) {
    #pragma unroll
    for (int o = 16; o > 0; o >>= 1)
        p += __shfl_xor_sync(0xffffffffu, p, o);
    __syncthreads();
    if ((tid & 31) == 0) red[tid >> 5] = p;
    __syncthreads();
    if (tid == 0) {
        float s = 0.f;
        #pragma unroll
        for (int i = 0; i < 8; i++) s += red[i];
        red[8] = s;
    }
    __syncthreads();
    return red[8];
}

__global__ __launch_bounds__(256) void k_squash(float* __restrict__ out) {
    const int bid = blockIdx.x;            // n0*128 + k*8 + n
    const int kn2 = bid & 127;             // k*8+n
    const int tid = threadIdx.x;

    __shared__ float red[9];

    float s0r[16], Ur[16];
    const float4* s0g = reinterpret_cast<const float4*>(&g_s0[bid * 4096]);
    const float4* Ug  = reinterpret_cast<const float4*>(&g_U[kn2 * 4096]);
    #pragma unroll
    for (int q = 0; q < 4; q++) {
        float4 v = s0g[tid + q * 256];
        s0r[q * 4 + 0] = v.x; s0r[q * 4 + 1] = v.y;
        s0r[q * 4 + 2] = v.z; s0r[q * 4 + 3] = v.w;
        float4 u = Ug[tid + q * 256];
        Ur[q * 4 + 0] = u.x; Ur[q * 4 + 1] = u.y;
        Ur[q * 4 + 2] = u.z; Ur[q * 4 + 3] = u.w;
    }

    float p, SS;

    p = 0.f;
    #pragma unroll
    for (int i = 0; i < 16; i++) p = fmaf(s0r[i], s0r[i], p);
    SS = block_reduce(p, red, tid);
    const float f0 = sqrtf(SS) / (1.f + SS);

    p = 0.f;
    #pragma unroll
    for (int i = 0; i < 16; i++) {
        float s1 = s0r[i] * (1.f + f0 * s0r[i] * Ur[i]);
        p = fmaf(s1, s1, p);
    }
    SS = block_reduce(p, red, tid);
    const float f1 = sqrtf(SS) / (1.f + SS);

    p = 0.f;
    #pragma unroll
    for (int i = 0; i < 16; i++) {
        float s1 = s0r[i] * (1.f + f0 * s0r[i] * Ur[i]);
        float s2 = s0r[i] + f1 * s1 * s1 * Ur[i];
        p = fmaf(s2, s2, p);
    }
    SS = block_reduce(p, red, tid);
    const float f2 = sqrtf(SS) / (1.f + SS);

    float4* orow = reinterpret_cast<float4*>(out + bid * 4096);
    #pragma unroll
    for (int q = 0; q < 4; q++) {
        float o[4];
        #pragma unroll
        for (int m = 0; m < 4; m++) {
            int i = q * 4 + m;
            float s1 = s0r[i] * (1.f + f0 * s0r[i] * Ur[i]);
            float s2 = s0r[i] + f1 * s1 * s1 * Ur[i];
            o[m] = f2 * s2;
        }
        orow[tid + q * 256] = make_float4(o[0], o[1], o[2], o[3]);
    }
}

// ---------------------------------------------------------------------------
extern "C" void kernel_launch(void* const* d_in, const int* in_sizes, int n_in,
                              void* d_out, int out_size) {
    const float* x      = (const float*)d_in[0];
    const float* conv_w = (const float*)d_in[1];
    const float* conv_b = (const float*)d_in[2];
    const float* caps_w = (const float*)d_in[3];
    const float* caps_b = (const float*)d_in[4];
    const float* W      = (const float*)d_in[5];
    float* out = (float*)d_out;

    k_pre<<<641, 160>>>(x, W, caps_w, conv_w, conv_b, caps_b);
    k_conv<<<dim3(16, 144), 128>>>();
    k_squash<<<1024, 256>>>(out);
}